// round 6
// baseline (speedup 1.0000x reference)
#include <cuda_runtime.h>
#include <math.h>

#define N 512
#define M 512
#define D 512
#define HG 256
#define R 256
#define H 128

// ---------------- device scratch ----------------
__device__ float d_hid[3 * N][HG];   // gelu(X@w1+b1)
__device__ float d_rep[3][N][R];
__device__ float d_norm2[3][N];
__device__ float d_Wxd[R * H];
__device__ float d_Wyd[R * H];
__device__ float d_A[N * H];
__device__ float d_Bt[2][H * M];
__device__ float d_G[2][N * M];
__device__ float d_W[2][N * M];
__device__ float d_Upart[4][N][R];

#define INV_SQRT2 0.7071067811865476f

__device__ __forceinline__ float gelu_exact(float x) {
    return 0.5f * x * (1.0f + erff(x * INV_SQRT2));
}

__device__ __forceinline__ float erf_fast(float x) {
    float ax = fabsf(x);
    float t;
    asm("rcp.approx.f32 %0, %1;" : "=f"(t) : "f"(fmaf(0.3275911f, ax, 1.0f)));
    float p = fmaf(1.061405429f, t, -1.453152027f);
    p = fmaf(p, t, 1.421413741f);
    p = fmaf(p, t, -0.284496736f);
    p = fmaf(p, t, 0.254829592f);
    p = p * t;
    float ex = __expf(-ax * ax);
    float r = fmaf(-p, ex, 1.0f);
    return copysignf(r, x);
}

// ================= K1a: hidden = gelu(X@w1+b1), double-buffered GEMM =================
// grid = 96 row-tiles(16) x 4 col-tiles(64) = 384 blocks + 32 wcomb = 416, 256 threads
__global__ void __launch_bounds__(256) k1a_hidden(
    const float* __restrict__ fx, const float* __restrict__ fp, const float* __restrict__ fn,
    const float* __restrict__ w1, const float* __restrict__ b1,
    const float* __restrict__ s_w1)
{
    int bid = blockIdx.x;
    int tid = threadIdx.x;

    if (bid >= 384) {  // wcomb
        int i0 = (bid - 384) * 1024 + tid;
#pragma unroll
        for (int t = 0; t < 4; t++) {
            int i = i0 + t * 256;
            float wd = s_w1[2 * R * H + i];
            d_Wxd[i] = s_w1[i] - wd;
            d_Wyd[i] = s_w1[R * H + i] + wd;
        }
        return;
    }

    int row0 = (bid >> 2) * 16;
    int col0 = (bid & 3) * 64;
    const float* X = (row0 < 512) ? fx : (row0 < 1024 ? fp : fn);
    int xrow0 = row0 & 511;

    __shared__ float xs[2][32][17];
    __shared__ float ws[2][32][64];

    int ty = tid >> 4;
    int tx = tid & 15;

    float acc0 = 0.f, acc1 = 0.f, acc2 = 0.f, acc3 = 0.f;
    float xr[2], wr[8];
#pragma unroll
    for (int p = 0; p < 2; p++) { int idx = tid + p * 256; xr[p] = X[(xrow0 + (idx >> 5)) * D + (idx & 31)]; }
#pragma unroll
    for (int p = 0; p < 8; p++) { int idx = tid + p * 256; wr[p] = w1[(idx >> 6) * HG + col0 + (idx & 63)]; }
#pragma unroll
    for (int p = 0; p < 2; p++) { int idx = tid + p * 256; xs[0][idx & 31][idx >> 5] = xr[p]; }
#pragma unroll
    for (int p = 0; p < 8; p++) { int idx = tid + p * 256; ws[0][idx >> 6][idx & 63] = wr[p]; }
    __syncthreads();

    int buf = 0;
    for (int kc = 0; kc < 16; kc++) {
        if (kc < 15) {
            int k0 = (kc + 1) * 32;
#pragma unroll
            for (int p = 0; p < 2; p++) { int idx = tid + p * 256; xr[p] = X[(xrow0 + (idx >> 5)) * D + k0 + (idx & 31)]; }
#pragma unroll
            for (int p = 0; p < 8; p++) { int idx = tid + p * 256; wr[p] = w1[(k0 + (idx >> 6)) * HG + col0 + (idx & 63)]; }
        }
#pragma unroll
        for (int kk = 0; kk < 32; kk++) {
            float xv = xs[buf][kk][ty];
            float4 wv = *(const float4*)&ws[buf][kk][tx * 4];
            acc0 = fmaf(xv, wv.x, acc0);
            acc1 = fmaf(xv, wv.y, acc1);
            acc2 = fmaf(xv, wv.z, acc2);
            acc3 = fmaf(xv, wv.w, acc3);
        }
        if (kc < 15) {
            __syncthreads();
            int nb = buf ^ 1;
#pragma unroll
            for (int p = 0; p < 2; p++) { int idx = tid + p * 256; xs[nb][idx & 31][idx >> 5] = xr[p]; }
#pragma unroll
            for (int p = 0; p < 8; p++) { int idx = tid + p * 256; ws[nb][idx >> 6][idx & 63] = wr[p]; }
            __syncthreads();
            buf = nb;
        }
    }
    float4 bb = *(const float4*)&b1[col0 + tx * 4];
    float4 o;
    o.x = gelu_exact(acc0 + bb.x);
    o.y = gelu_exact(acc1 + bb.y);
    o.z = gelu_exact(acc2 + bb.z);
    o.w = gelu_exact(acc3 + bb.w);
    *(float4*)&d_hid[row0 + ty][col0 + tx * 4] = o;
}

// ================= K1b: rep = hid@w2 + b2, double-buffered GEMM =================
// grid = 96 x 4 = 384 blocks, 256 threads
__global__ void __launch_bounds__(256) k1b_rep(
    const float* __restrict__ w2, const float* __restrict__ b2)
{
    int bid = blockIdx.x;
    int tid = threadIdx.x;
    int row0 = (bid >> 2) * 16;
    int col0 = (bid & 3) * 64;
    float* repf = &d_rep[0][0][0];

    __shared__ float xs[2][32][17];
    __shared__ float ws[2][32][64];

    int ty = tid >> 4;
    int tx = tid & 15;

    float acc0 = 0.f, acc1 = 0.f, acc2 = 0.f, acc3 = 0.f;
    float xr[2], wr[8];
#pragma unroll
    for (int p = 0; p < 2; p++) { int idx = tid + p * 256; xr[p] = d_hid[row0 + (idx >> 5)][idx & 31]; }
#pragma unroll
    for (int p = 0; p < 8; p++) { int idx = tid + p * 256; wr[p] = w2[(idx >> 6) * R + col0 + (idx & 63)]; }
#pragma unroll
    for (int p = 0; p < 2; p++) { int idx = tid + p * 256; xs[0][idx & 31][idx >> 5] = xr[p]; }
#pragma unroll
    for (int p = 0; p < 8; p++) { int idx = tid + p * 256; ws[0][idx >> 6][idx & 63] = wr[p]; }
    __syncthreads();

    int buf = 0;
    for (int kc = 0; kc < 8; kc++) {
        if (kc < 7) {
            int k0 = (kc + 1) * 32;
#pragma unroll
            for (int p = 0; p < 2; p++) { int idx = tid + p * 256; xr[p] = d_hid[row0 + (idx >> 5)][k0 + (idx & 31)]; }
#pragma unroll
            for (int p = 0; p < 8; p++) { int idx = tid + p * 256; wr[p] = w2[(k0 + (idx >> 6)) * R + col0 + (idx & 63)]; }
        }
#pragma unroll
        for (int kk = 0; kk < 32; kk++) {
            float xv = xs[buf][kk][ty];
            float4 wv = *(const float4*)&ws[buf][kk][tx * 4];
            acc0 = fmaf(xv, wv.x, acc0);
            acc1 = fmaf(xv, wv.y, acc1);
            acc2 = fmaf(xv, wv.z, acc2);
            acc3 = fmaf(xv, wv.w, acc3);
        }
        if (kc < 7) {
            __syncthreads();
            int nb = buf ^ 1;
#pragma unroll
            for (int p = 0; p < 2; p++) { int idx = tid + p * 256; xs[nb][idx & 31][idx >> 5] = xr[p]; }
#pragma unroll
            for (int p = 0; p < 8; p++) { int idx = tid + p * 256; ws[nb][idx >> 6][idx & 63] = wr[p]; }
            __syncthreads();
            buf = nb;
        }
    }
    float4 bb = *(const float4*)&b2[col0 + tx * 4];
    float4 o = make_float4(acc0 + bb.x, acc1 + bb.y, acc2 + bb.z, acc3 + bb.w);
    *(float4*)&repf[(row0 + ty) * R + col0 + tx * 4] = o;
}

// ================= K2: Gram + A/Bt + norms =================
// grid = 128 gram + 192 AB + 48 norm = 368 blocks, 256 threads
__global__ void __launch_bounds__(256) k2_gram_ab(const float* __restrict__ s_b1)
{
    __shared__ float smbuf[2 * 32 * 68];
    int bid = blockIdx.x;
    int tid = threadIdx.x;

    if (bid < 128) {
        int set = bid >> 6;
        int tt = bid & 63;
        int bn = (tt >> 3) * 64;
        int bm = (tt & 7) * 64;
        float (*xs)[68]  = (float(*)[68])smbuf;
        float (*ysm)[68] = (float(*)[68])(smbuf + 32 * 68);
        int ty = tid >> 4, tx = tid & 15;

        float acc[4][4];
#pragma unroll
        for (int i = 0; i < 4; i++)
#pragma unroll
            for (int jj = 0; jj < 4; jj++) acc[i][jj] = 0.f;

        for (int kc = 0; kc < R / 32; kc++) {
            __syncthreads();
#pragma unroll
            for (int p = 0; p < 8; p++) {
                int i = tid + p * 256;
                int n = i >> 5, k = i & 31;
                xs[k][n]  = d_rep[0][bn + n][kc * 32 + k];
                ysm[k][n] = d_rep[set + 1][bm + n][kc * 32 + k];
            }
            __syncthreads();
#pragma unroll
            for (int k = 0; k < 32; k++) {
                float4 xv = *(const float4*)&xs[k][ty * 4];
                float4 yv = *(const float4*)&ysm[k][tx * 4];
                float xa[4] = {xv.x, xv.y, xv.z, xv.w};
                float ya[4] = {yv.x, yv.y, yv.z, yv.w};
#pragma unroll
                for (int i = 0; i < 4; i++)
#pragma unroll
                    for (int jj = 0; jj < 4; jj++) acc[i][jj] += xa[i] * ya[jj];
            }
        }
#pragma unroll
        for (int i = 0; i < 4; i++) {
            float4 o = make_float4(acc[i][0], acc[i][1], acc[i][2], acc[i][3]);
            *(float4*)&d_G[set][(bn + ty * 4 + i) * M + bm + tx * 4] = o;
        }
    } else if (bid < 320) {
        int ab = bid - 128;
        int mi = ab / 64;
        int r0 = (ab % 64) * 8;
        float (*ys)[R] = (float(*)[R])smbuf;
        float (*ps)[H] = (float(*)[H])(smbuf + 8 * R);

        for (int i = tid; i < 8 * R; i += 256)
            ys[i / R][i % R] = d_rep[mi][r0 + i / R][i % R];
        __syncthreads();

        int h = tid & 127;
        int half = tid >> 7;
        const float* Wc = (mi == 0) ? d_Wxd : d_Wyd;
        float acc[8];
#pragma unroll
        for (int r = 0; r < 8; r++) acc[r] = 0.f;
        int kbeg = half * 128;
#pragma unroll 4
        for (int k = kbeg; k < kbeg + 128; k++) {
            float wv = Wc[k * H + h];
#pragma unroll
            for (int r = 0; r < 8; r++) acc[r] += ys[r][k] * wv;
        }
        if (half == 1) {
#pragma unroll
            for (int r = 0; r < 8; r++) ps[r][h] = acc[r];
        }
        __syncthreads();
        if (half == 0) {
            if (mi == 0) {
                float bb = s_b1[h];
#pragma unroll
                for (int r = 0; r < 8; r++)
                    d_A[(r0 + r) * H + h] = (acc[r] + ps[r][h] + bb) * INV_SQRT2;
            } else {
#pragma unroll
                for (int r = 0; r < 8; r++)
                    d_Bt[mi - 1][h * M + (r0 + r)] = (acc[r] + ps[r][h]) * INV_SQRT2;
            }
        }
    } else {
        // norms: 48 blocks, 32 rows each; 8 threads per row
        int nb = bid - 320;
        int r = nb * 32 + (tid >> 3);
        int part = tid & 7;
        const float* repf = &d_rep[0][0][0];
        float s = 0.f;
#pragma unroll
        for (int j = 0; j < 8; j++) {
            float4 v = *(const float4*)&repf[r * R + part * 32 + j * 4];
            s += v.x * v.x + v.y * v.y + v.z * v.z + v.w * v.w;
        }
#pragma unroll
        for (int o = 4; o; o >>= 1) s += __shfl_xor_sync(0xFFFFFFFFu, s, o);
        if (part == 0) (&d_norm2[0][0])[r] = s;
    }
}

// ================= K3: score + softmax =================
__global__ void __launch_bounds__(256) k3_score(
    const float* __restrict__ s_w1, const float* __restrict__ s_w2)
{
    int set = blockIdx.x >> 8;
    int n0 = (blockIdx.x & 255) * 2;
    __shared__ float As[2][H];
    __shared__ float wn_s[H];
    __shared__ float s2h[H];
    __shared__ float logits[2][M];
    __shared__ float nxs[2];
    __shared__ float red[2][8];

    int tid = threadIdx.x;
    As[tid >> 7][tid & 127] = d_A[(n0 + (tid >> 7)) * H + (tid & 127)];
    if (tid < H) {
        wn_s[tid] = s_w1[(3 * R) * H + tid] * INV_SQRT2;
        s2h[tid]  = s_w2[tid] * 0.7071067811865476f;
    }
    if (tid < 2) nxs[tid] = d_norm2[0][n0 + tid];
    __syncthreads();

    int m0 = tid, m1 = tid + 256;
    float ny0 = d_norm2[set + 1][m0];
    float ny1 = d_norm2[set + 1][m1];
    float t00, t01, t10, t11;
    {
        float g00 = d_G[set][(n0 + 0) * M + m0];
        float g01 = d_G[set][(n0 + 0) * M + m1];
        float g10 = d_G[set][(n0 + 1) * M + m0];
        float g11 = d_G[set][(n0 + 1) * M + m1];
        t00 = sqrtf(fmaxf(nxs[0] + ny0 - 2.f * g00, 0.f));
        t01 = sqrtf(fmaxf(nxs[0] + ny1 - 2.f * g01, 0.f));
        t10 = sqrtf(fmaxf(nxs[1] + ny0 - 2.f * g10, 0.f));
        t11 = sqrtf(fmaxf(nxs[1] + ny1 - 2.f * g11, 0.f));
    }

    float acc00 = 0.f, acc01 = 0.f, acc10 = 0.f, acc11 = 0.f;
    const float* Bt = d_Bt[set];
#pragma unroll 4
    for (int k = 0; k < H; k++) {
        float wk = wn_s[k];
        float s2 = s2h[k];
        float bv0 = Bt[k * M + m0];
        float bv1 = Bt[k * M + m1];
        float a0 = As[0][k], a1 = As[1][k];
        float p00 = fmaf(t00, wk, a0 + bv0);
        float p01 = fmaf(t01, wk, a0 + bv1);
        float p10 = fmaf(t10, wk, a1 + bv0);
        float p11 = fmaf(t11, wk, a1 + bv1);
        float e00 = erf_fast(p00), e01 = erf_fast(p01);
        float e10 = erf_fast(p10), e11 = erf_fast(p11);
        float q00 = p00 * s2, q01 = p01 * s2;
        float q10 = p10 * s2, q11 = p11 * s2;
        acc00 = fmaf(q00, e00, acc00 + q00);
        acc01 = fmaf(q01, e01, acc01 + q01);
        acc10 = fmaf(q10, e10, acc10 + q10);
        acc11 = fmaf(q11, e11, acc11 + q11);
    }
    logits[0][m0] = acc00; logits[0][m1] = acc01;
    logits[1][m0] = acc10; logits[1][m1] = acc11;
    __syncthreads();

    int row = tid >> 7;
    int c = tid & 127;
    int w4 = (tid >> 5) & 3;
    int lane = tid & 31;
    float v0 = logits[row][c], v1 = logits[row][c + 128];
    float v2 = logits[row][c + 256], v3 = logits[row][c + 384];
    float mx = fmaxf(fmaxf(v0, v1), fmaxf(v2, v3));
#pragma unroll
    for (int o = 16; o; o >>= 1) mx = fmaxf(mx, __shfl_xor_sync(0xFFFFFFFFu, mx, o));
    if (lane == 0) red[row][w4] = mx;
    __syncthreads();
    mx = fmaxf(fmaxf(red[row][0], red[row][1]), fmaxf(red[row][2], red[row][3]));
    float e0 = __expf(v0 - mx), e1 = __expf(v1 - mx);
    float e2 = __expf(v2 - mx), e3 = __expf(v3 - mx);
    float s = e0 + e1 + e2 + e3;
#pragma unroll
    for (int o = 16; o; o >>= 1) s += __shfl_xor_sync(0xFFFFFFFFu, s, o);
    __syncthreads();
    if (lane == 0) red[row][w4 + 4] = s;
    __syncthreads();
    s = red[row][4] + red[row][5] + red[row][6] + red[row][7];
    float inv = 1.f / s;
    float* Wrow = &d_W[set][(n0 + row) * M];
    Wrow[c] = e0 * inv; Wrow[c + 128] = e1 * inv;
    Wrow[c + 256] = e2 * inv; Wrow[c + 384] = e3 * inv;
}

// ================= K4a: U partials, split-K over M, double-buffered =================
__global__ void __launch_bounds__(256) k4a_u()
{
    __shared__ float w_s[2][2][16][36];
    __shared__ float yp_s[2][16][64];
    __shared__ float yn_s[2][16][64];

    int bid = blockIdx.x;
    int ms = bid & 3;
    int tile = bid >> 2;
    int bn = (tile >> 2) * 32;
    int br = (tile & 3) * 64;
    int tid = threadIdx.x;
    int ty = tid >> 4;
    int tx = tid & 15;

    int wset = tid >> 7;
    int wn = (tid & 127) >> 2;
    int wm = (tid & 3) * 4;
    int ykk = tid >> 4;
    int yc = (tid & 15) * 4;

    float acc[2][4];
#pragma unroll
    for (int i = 0; i < 2; i++)
#pragma unroll
        for (int j = 0; j < 4; j++) acc[i][j] = 0.f;

    int mbase = ms * 128;
    float4 wv, ypv, ynv;
    wv  = *(const float4*)&d_W[wset][(bn + wn) * M + mbase + wm];
    ypv = *(const float4*)&d_rep[1][mbase + ykk][br + yc];
    ynv = *(const float4*)&d_rep[2][mbase + ykk][br + yc];
    w_s[0][wset][wm + 0][wn] = wv.x;
    w_s[0][wset][wm + 1][wn] = wv.y;
    w_s[0][wset][wm + 2][wn] = wv.z;
    w_s[0][wset][wm + 3][wn] = wv.w;
    *(float4*)&yp_s[0][ykk][yc] = ypv;
    *(float4*)&yn_s[0][ykk][yc] = ynv;
    __syncthreads();

    int buf = 0;
    for (int mc = 0; mc < 8; mc++) {
        if (mc < 7) {
            int mrow = mbase + (mc + 1) * 16;
            wv  = *(const float4*)&d_W[wset][(bn + wn) * M + mrow + wm];
            ypv = *(const float4*)&d_rep[1][mrow + ykk][br + yc];
            ynv = *(const float4*)&d_rep[2][mrow + ykk][br + yc];
        }
#pragma unroll
        for (int kk = 0; kk < 16; kk++) {
            float wp0 = w_s[buf][0][kk][ty * 2], wp1 = w_s[buf][0][kk][ty * 2 + 1];
            float wq0 = w_s[buf][1][kk][ty * 2], wq1 = w_s[buf][1][kk][ty * 2 + 1];
            float4 yp = *(const float4*)&yp_s[buf][kk][tx * 4];
            float4 yn = *(const float4*)&yn_s[buf][kk][tx * 4];
            float ypa[4] = {yp.x, yp.y, yp.z, yp.w};
            float yna[4] = {yn.x, yn.y, yn.z, yn.w};
#pragma unroll
            for (int j = 0; j < 4; j++) {
                acc[0][j] += wp0 * ypa[j];
                acc[1][j] += wp1 * ypa[j];
                acc[0][j] -= wq0 * yna[j];
                acc[1][j] -= wq1 * yna[j];
            }
        }
        if (mc < 7) {
            __syncthreads();
            int nb = buf ^ 1;
            w_s[nb][wset][wm + 0][wn] = wv.x;
            w_s[nb][wset][wm + 1][wn] = wv.y;
            w_s[nb][wset][wm + 2][wn] = wv.z;
            w_s[nb][wset][wm + 3][wn] = wv.w;
            *(float4*)&yp_s[nb][ykk][yc] = ypv;
            *(float4*)&yn_s[nb][ykk][yc] = ynv;
            __syncthreads();
            buf = nb;
        }
    }
#pragma unroll
    for (int i = 0; i < 2; i++) {
        float4 o = make_float4(acc[i][0], acc[i][1], acc[i][2], acc[i][3]);
        *(float4*)&d_Upart[ms][bn + ty * 2 + i][br + tx * 4] = o;
    }
}

// ================= K4b: out = (sum of U partials) @ out_w =================
__global__ void __launch_bounds__(256) k4b_out(const float* __restrict__ out_w,
                                               float* __restrict__ out)
{
    __shared__ float us[16][36];
    __shared__ float ws[16][64];

    int bid = blockIdx.x;
    int bn = (bid >> 3) * 32;
    int bd = (bid & 7) * 64;
    int tid = threadIdx.x;
    int ty = tid >> 4, tx = tid & 15;

    float acc[2][4];
#pragma unroll
    for (int i = 0; i < 2; i++)
#pragma unroll
        for (int j = 0; j < 4; j++) acc[i][j] = 0.f;

    int un = tid >> 2;
    int uk = (tid & 3) * 4;
    int t2 = tid - 128;
    int wkk = t2 >> 3;
    int wc = (t2 & 7) * 8;

    for (int kc = 0; kc < R / 16; kc++) {
        float4 uv; float4 wv0, wv1;
        if (tid < 128) {
            float4 a = *(const float4*)&d_Upart[0][bn + un][kc * 16 + uk];
            float4 b = *(const float4*)&d_Upart[1][bn + un][kc * 16 + uk];
            float4 c = *(const float4*)&d_Upart[2][bn + un][kc * 16 + uk];
            float4 d = *(const float4*)&d_Upart[3][bn + un][kc * 16 + uk];
            uv.x = a.x + b.x + c.x + d.x;
            uv.y = a.y + b.y + c.y + d.y;
            uv.z = a.z + b.z + c.z + d.z;
            uv.w = a.w + b.w + c.w + d.w;
        } else {
            wv0 = *(const float4*)&out_w[(kc * 16 + wkk) * D + bd + wc];
            wv1 = *(const float4*)&out_w[(kc * 16 + wkk) * D + bd + wc + 4];
        }
        __syncthreads();
        if (tid < 128) {
            us[uk + 0][un] = uv.x;
            us[uk + 1][un] = uv.y;
            us[uk + 2][un] = uv.z;
            us[uk + 3][un] = uv.w;
        } else {
            *(float4*)&ws[wkk][wc] = wv0;
            *(float4*)&ws[wkk][wc + 4] = wv1;
        }
        __syncthreads();
#pragma unroll
        for (int kk = 0; kk < 16; kk++) {
            float u0 = us[kk][ty * 2], u1 = us[kk][ty * 2 + 1];
            float4 w4 = *(const float4*)&ws[kk][tx * 4];
            float wa[4] = {w4.x, w4.y, w4.z, w4.w};
#pragma unroll
            for (int j = 0; j < 4; j++) {
                acc[0][j] += u0 * wa[j];
                acc[1][j] += u1 * wa[j];
            }
        }
    }
#pragma unroll
    for (int i = 0; i < 2; i++) {
        float4 o = make_float4(acc[i][0], acc[i][1], acc[i][2], acc[i][3]);
        *(float4*)&out[(bn + ty * 2 + i) * D + bd + tx * 4] = o;
    }
}

// ---------------- launch ----------------
extern "C" void kernel_launch(void* const* d_in, const int* in_sizes, int n_in,
                              void* d_out, int out_size)
{
    const float* feat_x  = (const float*)d_in[0];
    const float* feat_pos= (const float*)d_in[1];
    const float* feat_neg= (const float*)d_in[2];
    const float* g_w1    = (const float*)d_in[3];
    const float* g_b1    = (const float*)d_in[4];
    const float* g_w2    = (const float*)d_in[5];
    const float* g_b2    = (const float*)d_in[6];
    const float* out_w   = (const float*)d_in[7];
    const float* s_w1    = (const float*)d_in[8];
    const float* s_b1    = (const float*)d_in[9];
    const float* s_w2    = (const float*)d_in[10];
    float* out = (float*)d_out;
    (void)in_sizes; (void)n_in; (void)out_size;

    k1a_hidden<<<416, 256>>>(feat_x, feat_pos, feat_neg, g_w1, g_b1, s_w1);
    k1b_rep<<<384, 256>>>(g_w2, g_b2);
    k2_gram_ab<<<368, 256>>>(s_b1);
    k3_score<<<512, 256>>>(s_w1, s_w2);
    k4a_u<<<256, 256>>>();
    k4b_out<<<128, 256>>>(out_w, out);
}

// round 7
// speedup vs baseline: 1.0458x; 1.0458x over previous
#include <cuda_runtime.h>
#include <math.h>

#define N 512
#define M 512
#define D 512
#define HG 256
#define R 256
#define H 128

typedef unsigned long long ull;

// ---------------- device scratch ----------------
__device__ float d_rep[3][N][R];
__device__ float d_norm2[3][N];
__device__ float d_Wxd[R * H];
__device__ float d_Wyd[R * H];
__device__ float d_A[N * H];        // pre-scaled by 1/sqrt(2)
__device__ float d_Bt[2][H * M];    // pre-scaled by 1/sqrt(2)
__device__ float d_G[2][N * M];
__device__ float d_W[2][N * M];
__device__ float d_Upart[4][N][R];

#define INV_SQRT2 0.7071067811865476f

__device__ __forceinline__ float gelu_exact(float x) {
    return 0.5f * x * (1.0f + erff(x * INV_SQRT2));
}

// ---------------- packed f32x2 helpers ----------------
__device__ __forceinline__ ull pk2(float x, float y) {
    ull r; asm("mov.b64 %0, {%1, %2};" : "=l"(r) : "f"(x), "f"(y)); return r;
}
__device__ __forceinline__ void upk2(ull v, float& x, float& y) {
    asm("mov.b64 {%0, %1}, %2;" : "=f"(x), "=f"(y) : "l"(v));
}
__device__ __forceinline__ ull f2fma(ull a, ull b, ull c) {
    ull d; asm("fma.rn.f32x2 %0, %1, %2, %3;" : "=l"(d) : "l"(a), "l"(b), "l"(c)); return d;
}
__device__ __forceinline__ ull f2add(ull a, ull b) {
    ull d; asm("add.rn.f32x2 %0, %1, %2;" : "=l"(d) : "l"(a), "l"(b)); return d;
}
__device__ __forceinline__ ull f2mul(ull a, ull b) {
    ull d; asm("mul.rn.f32x2 %0, %1, %2;" : "=l"(d) : "l"(a), "l"(b)); return d;
}
__device__ __forceinline__ ull f2rcp(ull a) {
    float lo, hi, rl, rh;
    asm("mov.b64 {%0, %1}, %2;" : "=f"(lo), "=f"(hi) : "l"(a));
    asm("rcp.approx.f32 %0, %1;" : "=f"(rl) : "f"(lo));
    asm("rcp.approx.f32 %0, %1;" : "=f"(rh) : "f"(hi));
    return pk2(rl, rh);
}
__device__ __forceinline__ ull f2ex2(ull a) {
    float lo, hi, rl, rh;
    asm("mov.b64 {%0, %1}, %2;" : "=f"(lo), "=f"(hi) : "l"(a));
    asm("ex2.approx.f32 %0, %1;" : "=f"(rl) : "f"(lo));
    asm("ex2.approx.f32 %0, %1;" : "=f"(rh) : "f"(hi));
    return pk2(rl, rh);
}

// ================= K1: fused g-MLP (+ norms) and Wxd/Wyd combine =================
__global__ void __launch_bounds__(256) k1_gmlp(
    const float* __restrict__ fx, const float* __restrict__ fp, const float* __restrict__ fn,
    const float* __restrict__ w1, const float* __restrict__ b1,
    const float* __restrict__ w2, const float* __restrict__ b2,
    const float* __restrict__ s_w1)
{
    int bid = blockIdx.x;
    int tid = threadIdx.x;

    if (bid >= 192) {
        int i0 = (bid - 192) * 1024 + tid;
#pragma unroll
        for (int t = 0; t < 4; t++) {
            int i = i0 + t * 256;
            float wd = s_w1[2 * R * H + i];
            d_Wxd[i] = s_w1[i] - wd;
            d_Wyd[i] = s_w1[R * H + i] + wd;
        }
        return;
    }

    int mi = bid / 64;
    int r0 = (bid % 64) * 8;
    const float* X = (mi == 0) ? fx : (mi == 1 ? fp : fn);

    __shared__ float xs[8][D];
    __shared__ float hs[8][HG];
    __shared__ float wsum[8][8];

    for (int i = tid; i < 8 * D; i += 256)
        xs[i / D][i % D] = X[(r0 + i / D) * D + (i % D)];
    __syncthreads();

    int j = tid;
    float acc[8];
#pragma unroll
    for (int r = 0; r < 8; r++) acc[r] = 0.f;
#pragma unroll 4
    for (int k = 0; k < D; k++) {
        float wv = w1[k * HG + j];
#pragma unroll
        for (int r = 0; r < 8; r++) acc[r] += xs[r][k] * wv;
    }
    float bb = b1[j];
#pragma unroll
    for (int r = 0; r < 8; r++) hs[r][j] = gelu_exact(acc[r] + bb);
    __syncthreads();

    float a2[8];
#pragma unroll
    for (int r = 0; r < 8; r++) a2[r] = 0.f;
#pragma unroll 4
    for (int k = 0; k < HG; k++) {
        float wv = w2[k * R + j];
#pragma unroll
        for (int r = 0; r < 8; r++) a2[r] += hs[r][k] * wv;
    }
    float b2v = b2[j];
    int w = tid >> 5, lane = tid & 31;
#pragma unroll
    for (int r = 0; r < 8; r++) {
        float v = a2[r] + b2v;
        d_rep[mi][r0 + r][j] = v;
        float s = v * v;
#pragma unroll
        for (int o = 16; o; o >>= 1) s += __shfl_xor_sync(0xFFFFFFFFu, s, o);
        if (lane == 0) wsum[w][r] = s;
    }
    __syncthreads();
    if (tid < 8) {
        float s = 0.f;
#pragma unroll
        for (int ww = 0; ww < 8; ww++) s += wsum[ww][tid];
        d_norm2[mi][r0 + tid] = s;
    }
}

// ================= K2: Gram (64x64) + A/Bt (split-K) =================
__global__ void __launch_bounds__(256) k2_gram_ab(const float* __restrict__ s_b1)
{
    __shared__ float smbuf[2 * 32 * 68];
    int bid = blockIdx.x;
    int tid = threadIdx.x;

    if (bid < 128) {
        int set = bid >> 6;
        int tt = bid & 63;
        int bn = (tt >> 3) * 64;
        int bm = (tt & 7) * 64;
        float (*xs)[68]  = (float(*)[68])smbuf;
        float (*ysm)[68] = (float(*)[68])(smbuf + 32 * 68);
        int ty = tid >> 4, tx = tid & 15;

        float acc[4][4];
#pragma unroll
        for (int i = 0; i < 4; i++)
#pragma unroll
            for (int jj = 0; jj < 4; jj++) acc[i][jj] = 0.f;

        for (int kc = 0; kc < R / 32; kc++) {
            __syncthreads();
#pragma unroll
            for (int p = 0; p < 8; p++) {
                int i = tid + p * 256;
                int n = i >> 5, k = i & 31;
                xs[k][n]  = d_rep[0][bn + n][kc * 32 + k];
                ysm[k][n] = d_rep[set + 1][bm + n][kc * 32 + k];
            }
            __syncthreads();
#pragma unroll
            for (int k = 0; k < 32; k++) {
                float4 xv = *(const float4*)&xs[k][ty * 4];
                float4 yv = *(const float4*)&ysm[k][tx * 4];
                float xa[4] = {xv.x, xv.y, xv.z, xv.w};
                float ya[4] = {yv.x, yv.y, yv.z, yv.w};
#pragma unroll
                for (int i = 0; i < 4; i++)
#pragma unroll
                    for (int jj = 0; jj < 4; jj++) acc[i][jj] += xa[i] * ya[jj];
            }
        }
#pragma unroll
        for (int i = 0; i < 4; i++) {
            float4 o = make_float4(acc[i][0], acc[i][1], acc[i][2], acc[i][3]);
            *(float4*)&d_G[set][(bn + ty * 4 + i) * M + bm + tx * 4] = o;
        }
    } else {
        int ab = bid - 128;
        int mi = ab / 64;
        int r0 = (ab % 64) * 8;
        float (*ys)[R] = (float(*)[R])smbuf;
        float (*ps)[H] = (float(*)[H])(smbuf + 8 * R);

        for (int i = tid; i < 8 * R; i += 256)
            ys[i / R][i % R] = d_rep[mi][r0 + i / R][i % R];
        __syncthreads();

        int h = tid & 127;
        int half = tid >> 7;
        const float* Wc = (mi == 0) ? d_Wxd : d_Wyd;
        float acc[8];
#pragma unroll
        for (int r = 0; r < 8; r++) acc[r] = 0.f;
        int kbeg = half * 128;
#pragma unroll 4
        for (int k = kbeg; k < kbeg + 128; k++) {
            float wv = Wc[k * H + h];
#pragma unroll
            for (int r = 0; r < 8; r++) acc[r] += ys[r][k] * wv;
        }
        if (half == 1) {
#pragma unroll
            for (int r = 0; r < 8; r++) ps[r][h] = acc[r];
        }
        __syncthreads();
        if (half == 0) {
            if (mi == 0) {
                float bb = s_b1[h];
#pragma unroll
                for (int r = 0; r < 8; r++)
                    d_A[(r0 + r) * H + h] = (acc[r] + ps[r][h] + bb) * INV_SQRT2;
            } else {
#pragma unroll
                for (int r = 0; r < 8; r++)
                    d_Bt[mi - 1][h * M + (r0 + r)] = (acc[r] + ps[r][h]) * INV_SQRT2;
            }
        }
    }
}

// ================= K3: score + softmax (packed f32x2 hot loop) =================
// thread handles m-pair (2*tid, 2*tid+1) for 2 n-rows
__global__ void __launch_bounds__(256) k3_score(
    const float* __restrict__ s_w1, const float* __restrict__ s_w2)
{
    int set = blockIdx.x >> 8;
    int n0 = (blockIdx.x & 255) * 2;
    __shared__ float2 As2[2][H];
    __shared__ float2 wn2[H];
    __shared__ float2 s22[H];
    __shared__ float logits[2][M];
    __shared__ float nxs[2];
    __shared__ float red[2][8];

    int tid = threadIdx.x;
    {
        int row = tid >> 7, k = tid & 127;
        float a = d_A[(n0 + row) * H + k];
        As2[row][k] = make_float2(a, a);
    }
    if (tid < H) {
        float w = s_w1[(3 * R) * H + tid] * INV_SQRT2;
        wn2[tid] = make_float2(w, w);
        float s2 = s_w2[tid] * 0.7071067811865476f;
        s22[tid] = make_float2(s2, s2);
    }
    if (tid < 2) nxs[tid] = d_norm2[0][n0 + tid];
    __syncthreads();

    // packed constants (A-S 7.1.26, coefficients pre-negated for 1 - p(t)e^{-x^2})
    const ull ONE2 = 0x3F8000003F800000ULL;
    const ull ABSM = 0x7FFFFFFF7FFFFFFFULL;
    const ull SGNM = 0x8000000080000000ULL;
    ull C_P  = pk2(0.3275911f, 0.3275911f);
    ull B5 = pk2(-1.061405429f, -1.061405429f);
    ull B4 = pk2( 1.453152027f,  1.453152027f);
    ull B3 = pk2(-1.421413741f, -1.421413741f);
    ull B2 = pk2( 0.284496736f,  0.284496736f);
    ull B1 = pk2(-0.254829592f, -0.254829592f);
    ull NL2E = pk2(-1.4426950408889634f, -1.4426950408889634f);

    // t (delta norms), packed per row
    ull t02, t12;
    {
        float2 ny = *(const float2*)&d_norm2[set + 1][tid * 2];
        float2 g0 = *(const float2*)&d_G[set][(n0 + 0) * M + tid * 2];
        float2 g1 = *(const float2*)&d_G[set][(n0 + 1) * M + tid * 2];
        float nx0 = nxs[0], nx1 = nxs[1];
        float t00 = sqrtf(fmaxf(nx0 + ny.x - 2.f * g0.x, 0.f));
        float t01 = sqrtf(fmaxf(nx0 + ny.y - 2.f * g0.y, 0.f));
        float t10 = sqrtf(fmaxf(nx1 + ny.x - 2.f * g1.x, 0.f));
        float t11 = sqrtf(fmaxf(nx1 + ny.y - 2.f * g1.y, 0.f));
        t02 = pk2(t00, t01);
        t12 = pk2(t10, t11);
    }

    ull acc0 = 0ULL, acc1 = 0ULL;  // {0,0}
    const ull* Btu = (const ull*)&d_Bt[set][0];    // [k*256 + tid]
    const ull* A0u = (const ull*)&As2[0][0];
    const ull* A1u = (const ull*)&As2[1][0];
    const ull* Wnu = (const ull*)&wn2[0];
    const ull* S2u = (const ull*)&s22[0];

#define ERF_ACC(P, ACC, S2V) do { \
        ull ax_ = (P) & ABSM; \
        ull tt_ = f2rcp(f2fma(C_P, ax_, ONE2)); \
        ull pl_ = f2fma(B5, tt_, B4); \
        pl_ = f2fma(pl_, tt_, B3); \
        pl_ = f2fma(pl_, tt_, B2); \
        pl_ = f2fma(pl_, tt_, B1); \
        pl_ = f2mul(pl_, tt_); \
        ull ex_ = f2ex2(f2mul(f2mul(ax_, ax_), NL2E)); \
        ull er_ = f2fma(pl_, ex_, ONE2); \
        er_ = er_ | ((P) & SGNM); \
        ull q_ = f2mul((P), (S2V)); \
        ACC = f2add(ACC, q_); \
        ACC = f2fma(q_, er_, ACC); \
    } while (0)

#pragma unroll 2
    for (int k = 0; k < H; k++) {
        ull bv2 = Btu[k * 256 + tid];
        ull wk2 = Wnu[k];
        ull s2v = S2u[k];
        ull p0 = f2fma(t02, wk2, f2add(A0u[k], bv2));
        ull p1 = f2fma(t12, wk2, f2add(A1u[k], bv2));
        ERF_ACC(p0, acc0, s2v);
        ERF_ACC(p1, acc1, s2v);
    }
#undef ERF_ACC

    {
        float l00, l01, l10, l11;
        upk2(acc0, l00, l01);
        upk2(acc1, l10, l11);
        *(float2*)&logits[0][tid * 2] = make_float2(l00, l01);
        *(float2*)&logits[1][tid * 2] = make_float2(l10, l11);
    }
    __syncthreads();

    int row = tid >> 7;
    int c = tid & 127;
    int w4 = (tid >> 5) & 3;
    int lane = tid & 31;
    float v0 = logits[row][c], v1 = logits[row][c + 128];
    float v2 = logits[row][c + 256], v3 = logits[row][c + 384];
    float mx = fmaxf(fmaxf(v0, v1), fmaxf(v2, v3));
#pragma unroll
    for (int o = 16; o; o >>= 1) mx = fmaxf(mx, __shfl_xor_sync(0xFFFFFFFFu, mx, o));
    if (lane == 0) red[row][w4] = mx;
    __syncthreads();
    mx = fmaxf(fmaxf(red[row][0], red[row][1]), fmaxf(red[row][2], red[row][3]));
    float e0 = __expf(v0 - mx), e1 = __expf(v1 - mx);
    float e2 = __expf(v2 - mx), e3 = __expf(v3 - mx);
    float s = e0 + e1 + e2 + e3;
#pragma unroll
    for (int o = 16; o; o >>= 1) s += __shfl_xor_sync(0xFFFFFFFFu, s, o);
    __syncthreads();
    if (lane == 0) red[row][w4 + 4] = s;
    __syncthreads();
    s = red[row][4] + red[row][5] + red[row][6] + red[row][7];
    float inv = 1.f / s;
    float* Wrow = &d_W[set][(n0 + row) * M];
    Wrow[c] = e0 * inv; Wrow[c + 128] = e1 * inv;
    Wrow[c + 256] = e2 * inv; Wrow[c + 384] = e3 * inv;
}

// ================= K4a: U partials, split-K over M, double-buffered =================
__global__ void __launch_bounds__(256) k4a_u()
{
    __shared__ float w_s[2][2][16][36];
    __shared__ float yp_s[2][16][64];
    __shared__ float yn_s[2][16][64];

    int bid = blockIdx.x;
    int ms = bid & 3;
    int tile = bid >> 2;
    int bn = (tile >> 2) * 32;
    int br = (tile & 3) * 64;
    int tid = threadIdx.x;
    int ty = tid >> 4;
    int tx = tid & 15;

    int wset = tid >> 7;
    int wn = (tid & 127) >> 2;
    int wm = (tid & 3) * 4;
    int ykk = tid >> 4;
    int yc = (tid & 15) * 4;

    float acc[2][4];
#pragma unroll
    for (int i = 0; i < 2; i++)
#pragma unroll
        for (int j = 0; j < 4; j++) acc[i][j] = 0.f;

    int mbase = ms * 128;
    float4 wv, ypv, ynv;
    wv  = *(const float4*)&d_W[wset][(bn + wn) * M + mbase + wm];
    ypv = *(const float4*)&d_rep[1][mbase + ykk][br + yc];
    ynv = *(const float4*)&d_rep[2][mbase + ykk][br + yc];
    w_s[0][wset][wm + 0][wn] = wv.x;
    w_s[0][wset][wm + 1][wn] = wv.y;
    w_s[0][wset][wm + 2][wn] = wv.z;
    w_s[0][wset][wm + 3][wn] = wv.w;
    *(float4*)&yp_s[0][ykk][yc] = ypv;
    *(float4*)&yn_s[0][ykk][yc] = ynv;
    __syncthreads();

    int buf = 0;
    for (int mc = 0; mc < 8; mc++) {
        if (mc < 7) {
            int mrow = mbase + (mc + 1) * 16;
            wv  = *(const float4*)&d_W[wset][(bn + wn) * M + mrow + wm];
            ypv = *(const float4*)&d_rep[1][mrow + ykk][br + yc];
            ynv = *(const float4*)&d_rep[2][mrow + ykk][br + yc];
        }
#pragma unroll
        for (int kk = 0; kk < 16; kk++) {
            float wp0 = w_s[buf][0][kk][ty * 2], wp1 = w_s[buf][0][kk][ty * 2 + 1];
            float wq0 = w_s[buf][1][kk][ty * 2], wq1 = w_s[buf][1][kk][ty * 2 + 1];
            float4 yp = *(const float4*)&yp_s[buf][kk][tx * 4];
            float4 yn = *(const float4*)&yn_s[buf][kk][tx * 4];
            float ypa[4] = {yp.x, yp.y, yp.z, yp.w};
            float yna[4] = {yn.x, yn.y, yn.z, yn.w};
#pragma unroll
            for (int j = 0; j < 4; j++) {
                acc[0][j] += wp0 * ypa[j];
                acc[1][j] += wp1 * ypa[j];
                acc[0][j] -= wq0 * yna[j];
                acc[1][j] -= wq1 * yna[j];
            }
        }
        if (mc < 7) {
            __syncthreads();
            int nb = buf ^ 1;
            w_s[nb][wset][wm + 0][wn] = wv.x;
            w_s[nb][wset][wm + 1][wn] = wv.y;
            w_s[nb][wset][wm + 2][wn] = wv.z;
            w_s[nb][wset][wm + 3][wn] = wv.w;
            *(float4*)&yp_s[nb][ykk][yc] = ypv;
            *(float4*)&yn_s[nb][ykk][yc] = ynv;
            __syncthreads();
            buf = nb;
        }
    }
#pragma unroll
    for (int i = 0; i < 2; i++) {
        float4 o = make_float4(acc[i][0], acc[i][1], acc[i][2], acc[i][3]);
        *(float4*)&d_Upart[ms][bn + ty * 2 + i][br + tx * 4] = o;
    }
}

// ================= K4b: out = (sum of U partials) @ out_w =================
__global__ void __launch_bounds__(256) k4b_out(const float* __restrict__ out_w,
                                               float* __restrict__ out)
{
    __shared__ float us[16][36];
    __shared__ float ws[16][64];

    int bid = blockIdx.x;
    int bn = (bid >> 3) * 32;
    int bd = (bid & 7) * 64;
    int tid = threadIdx.x;
    int ty = tid >> 4, tx = tid & 15;

    float acc[2][4];
#pragma unroll
    for (int i = 0; i < 2; i++)
#pragma unroll
        for (int j = 0; j < 4; j++) acc[i][j] = 0.f;

    int un = tid >> 2;
    int uk = (tid & 3) * 4;
    int t2 = tid - 128;
    int wkk = t2 >> 3;
    int wc = (t2 & 7) * 8;

    for (int kc = 0; kc < R / 16; kc++) {
        float4 uv; float4 wv0, wv1;
        if (tid < 128) {
            float4 a = *(const float4*)&d_Upart[0][bn + un][kc * 16 + uk];
            float4 b = *(const float4*)&d_Upart[1][bn + un][kc * 16 + uk];
            float4 c = *(const float4*)&d_Upart[2][bn + un][kc * 16 + uk];
            float4 d = *(const float4*)&d_Upart[3][bn + un][kc * 16 + uk];
            uv.x = a.x + b.x + c.x + d.x;
            uv.y = a.y + b.y + c.y + d.y;
            uv.z = a.z + b.z + c.z + d.z;
            uv.w = a.w + b.w + c.w + d.w;
        } else {
            wv0 = *(const float4*)&out_w[(kc * 16 + wkk) * D + bd + wc];
            wv1 = *(const float4*)&out_w[(kc * 16 + wkk) * D + bd + wc + 4];
        }
        __syncthreads();
        if (tid < 128) {
            us[uk + 0][un] = uv.x;
            us[uk + 1][un] = uv.y;
            us[uk + 2][un] = uv.z;
            us[uk + 3][un] = uv.w;
        } else {
            *(float4*)&ws[wkk][wc] = wv0;
            *(float4*)&ws[wkk][wc + 4] = wv1;
        }
        __syncthreads();
#pragma unroll
        for (int kk = 0; kk < 16; kk++) {
            float u0 = us[kk][ty * 2], u1 = us[kk][ty * 2 + 1];
            float4 w4 = *(const float4*)&ws[kk][tx * 4];
            float wa[4] = {w4.x, w4.y, w4.z, w4.w};
#pragma unroll
            for (int j = 0; j < 4; j++) {
                acc[0][j] += u0 * wa[j];
                acc[1][j] += u1 * wa[j];
            }
        }
    }
#pragma unroll
    for (int i = 0; i < 2; i++) {
        float4 o = make_float4(acc[i][0], acc[i][1], acc[i][2], acc[i][3]);
        *(float4*)&out[(bn + ty * 2 + i) * D + bd + tx * 4] = o;
    }
}

// ---------------- launch ----------------
extern "C" void kernel_launch(void* const* d_in, const int* in_sizes, int n_in,
                              void* d_out, int out_size)
{
    const float* feat_x  = (const float*)d_in[0];
    const float* feat_pos= (const float*)d_in[1];
    const float* feat_neg= (const float*)d_in[2];
    const float* g_w1    = (const float*)d_in[3];
    const float* g_b1    = (const float*)d_in[4];
    const float* g_w2    = (const float*)d_in[5];
    const float* g_b2    = (const float*)d_in[6];
    const float* out_w   = (const float*)d_in[7];
    const float* s_w1    = (const float*)d_in[8];
    const float* s_b1    = (const float*)d_in[9];
    const float* s_w2    = (const float*)d_in[10];
    float* out = (float*)d_out;
    (void)in_sizes; (void)n_in; (void)out_size;

    k1_gmlp<<<224, 256>>>(feat_x, feat_pos, feat_neg, g_w1, g_b1, g_w2, g_b2, s_w1);
    k2_gram_ab<<<320, 256>>>(s_b1);
    k3_score<<<512, 256>>>(s_w1, s_w2);
    k4a_u<<<256, 256>>>();
    k4b_out<<<128, 256>>>(out_w, out);
}

// round 8
// speedup vs baseline: 1.2074x; 1.1545x over previous
#include <cuda_runtime.h>
#include <math.h>

#define N 512
#define M 512
#define D 512
#define HG 256
#define R 256
#define H 128

// ---------------- device scratch ----------------
__device__ float d_rep[3][N][R];
__device__ float d_norm2[3][N];
__device__ float d_Wxd[R * H];
__device__ float d_Wyd[R * H];
__device__ float d_A[N * H];        // pre-scaled by 1/sqrt(2)
__device__ float d_Bt[2][H * M];    // pre-scaled by 1/sqrt(2)
__device__ float d_G[2][2][N * M];  // gram split-K partials
__device__ float d_W[2][N * M];
__device__ float d_Upart[8][N][R];
__device__ float d_Qb[2][M];        // sum_k s2h * Bt[k][m]
__device__ float d_Qw;              // sum_k s2h * wnh

#define INV_SQRT2 0.7071067811865476f

__device__ __forceinline__ float gelu_exact(float x) {
    return 0.5f * x * (1.0f + erff(x * INV_SQRT2));
}

// ================= K1: fused g-MLP, Wxd/Wyd combine, Qw =================
// grid = 192 mlp + 32 wcomb + 1 qw = 225 blocks, 256 threads
__global__ void __launch_bounds__(256) k1_gmlp(
    const float* __restrict__ fx, const float* __restrict__ fp, const float* __restrict__ fn,
    const float* __restrict__ w1, const float* __restrict__ b1,
    const float* __restrict__ w2, const float* __restrict__ b2,
    const float* __restrict__ s_w1, const float* __restrict__ s_w2)
{
    int bid = blockIdx.x;
    int tid = threadIdx.x;
    __shared__ float qr[4];

    if (bid == 224) {
        // Qw = sum_k 0.5 * s_w2[k] * wn[k]
        float v = 0.f;
        if (tid < 128) v = 0.5f * s_w2[tid] * s_w1[3 * R * H + tid];
#pragma unroll
        for (int o = 16; o; o >>= 1) v += __shfl_xor_sync(0xFFFFFFFFu, v, o);
        if (tid < 128 && (tid & 31) == 0) qr[tid >> 5] = v;
        __syncthreads();
        if (tid == 0) d_Qw = qr[0] + qr[1] + qr[2] + qr[3];
        return;
    }
    if (bid >= 192) {
        int i0 = (bid - 192) * 1024 + tid;
#pragma unroll
        for (int t = 0; t < 4; t++) {
            int i = i0 + t * 256;
            float wd = s_w1[2 * R * H + i];
            d_Wxd[i] = s_w1[i] - wd;
            d_Wyd[i] = s_w1[R * H + i] + wd;
        }
        return;
    }

    int mi = bid / 64;
    int r0 = (bid % 64) * 8;
    const float* X = (mi == 0) ? fx : (mi == 1 ? fp : fn);

    __shared__ float xs[8][D];
    __shared__ float hs[8][HG];
    __shared__ float wsum[8][8];

    for (int i = tid; i < 8 * D; i += 256)
        xs[i / D][i % D] = X[(r0 + i / D) * D + (i % D)];
    __syncthreads();

    int j = tid;
    float acc[8];
#pragma unroll
    for (int r = 0; r < 8; r++) acc[r] = 0.f;
#pragma unroll 4
    for (int k = 0; k < D; k++) {
        float wv = w1[k * HG + j];
#pragma unroll
        for (int r = 0; r < 8; r++) acc[r] += xs[r][k] * wv;
    }
    float bb = b1[j];
#pragma unroll
    for (int r = 0; r < 8; r++) hs[r][j] = gelu_exact(acc[r] + bb);
    __syncthreads();

    float a2[8];
#pragma unroll
    for (int r = 0; r < 8; r++) a2[r] = 0.f;
#pragma unroll 4
    for (int k = 0; k < HG; k++) {
        float wv = w2[k * R + j];
#pragma unroll
        for (int r = 0; r < 8; r++) a2[r] += hs[r][k] * wv;
    }
    float b2v = b2[j];
    int w = tid >> 5, lane = tid & 31;
#pragma unroll
    for (int r = 0; r < 8; r++) {
        float v = a2[r] + b2v;
        d_rep[mi][r0 + r][j] = v;
        float s = v * v;
#pragma unroll
        for (int o = 16; o; o >>= 1) s += __shfl_xor_sync(0xFFFFFFFFu, s, o);
        if (lane == 0) wsum[w][r] = s;
    }
    __syncthreads();
    if (tid < 8) {
        float s = 0.f;
#pragma unroll
        for (int ww = 0; ww < 8; ww++) s += wsum[ww][tid];
        d_norm2[mi][r0 + tid] = s;
    }
}

// ================= K2: Gram (split-K) + A/Bt (+Qb) =================
// grid = 256 gram + 192 AB = 448 blocks, 256 threads
__global__ void __launch_bounds__(256) k2_gram_ab(
    const float* __restrict__ s_b1, const float* __restrict__ s_w2)
{
    __shared__ float smbuf[2 * 32 * 68];
    __shared__ float qred[4][8];
    int bid = blockIdx.x;
    int tid = threadIdx.x;

    if (bid < 256) {
        // gram: bid = set(2) x khalf(2) x tile(64)
        int set = bid >> 7;
        int kh = (bid >> 6) & 1;
        int tt = bid & 63;
        int bn = (tt >> 3) * 64;
        int bm = (tt & 7) * 64;
        float (*xs)[68]  = (float(*)[68])smbuf;
        float (*ysm)[68] = (float(*)[68])(smbuf + 32 * 68);
        int ty = tid >> 4, tx = tid & 15;

        float acc[4][4];
#pragma unroll
        for (int i = 0; i < 4; i++)
#pragma unroll
            for (int jj = 0; jj < 4; jj++) acc[i][jj] = 0.f;

        for (int kc = kh * 4; kc < kh * 4 + 4; kc++) {
            __syncthreads();
#pragma unroll
            for (int p = 0; p < 8; p++) {
                int i = tid + p * 256;
                int n = i >> 5, k = i & 31;
                xs[k][n]  = d_rep[0][bn + n][kc * 32 + k];
                ysm[k][n] = d_rep[set + 1][bm + n][kc * 32 + k];
            }
            __syncthreads();
#pragma unroll
            for (int k = 0; k < 32; k++) {
                float4 xv = *(const float4*)&xs[k][ty * 4];
                float4 yv = *(const float4*)&ysm[k][tx * 4];
                float xa[4] = {xv.x, xv.y, xv.z, xv.w};
                float ya[4] = {yv.x, yv.y, yv.z, yv.w};
#pragma unroll
                for (int i = 0; i < 4; i++)
#pragma unroll
                    for (int jj = 0; jj < 4; jj++) acc[i][jj] += xa[i] * ya[jj];
            }
        }
#pragma unroll
        for (int i = 0; i < 4; i++) {
            float4 o = make_float4(acc[i][0], acc[i][1], acc[i][2], acc[i][3]);
            *(float4*)&d_G[set][kh][(bn + ty * 4 + i) * M + bm + tx * 4] = o;
        }
    } else {
        int ab = bid - 256;
        int mi = ab / 64;
        int r0 = (ab % 64) * 8;
        float (*ys)[R] = (float(*)[R])smbuf;
        float (*ps)[H] = (float(*)[H])(smbuf + 8 * R);

        for (int i = tid; i < 8 * R; i += 256)
            ys[i / R][i % R] = d_rep[mi][r0 + i / R][i % R];
        __syncthreads();

        int h = tid & 127;
        int half = tid >> 7;
        const float* Wc = (mi == 0) ? d_Wxd : d_Wyd;
        float acc[8];
#pragma unroll
        for (int r = 0; r < 8; r++) acc[r] = 0.f;
        int kbeg = half * 128;
#pragma unroll 4
        for (int k = kbeg; k < kbeg + 128; k++) {
            float wv = Wc[k * H + h];
#pragma unroll
            for (int r = 0; r < 8; r++) acc[r] += ys[r][k] * wv;
        }
        if (half == 1) {
#pragma unroll
            for (int r = 0; r < 8; r++) ps[r][h] = acc[r];
        }
        __syncthreads();
        if (half == 0) {
            if (mi == 0) {
                float bb = s_b1[h];
#pragma unroll
                for (int r = 0; r < 8; r++)
                    d_A[(r0 + r) * H + h] = (acc[r] + ps[r][h] + bb) * INV_SQRT2;
            } else {
                float s2h = 0.70710678f * s_w2[h];
                int w = tid >> 5, lane = tid & 31;
#pragma unroll
                for (int r = 0; r < 8; r++) {
                    float btv = (acc[r] + ps[r][h]) * INV_SQRT2;
                    d_Bt[mi - 1][h * M + (r0 + r)] = btv;
                    float pr = s2h * btv;
#pragma unroll
                    for (int o = 16; o; o >>= 1) pr += __shfl_xor_sync(0xFFFFFFFFu, pr, o);
                    if (lane == 0) qred[w][r] = pr;
                }
            }
        }
        __syncthreads();
        if (mi > 0 && tid < 8)
            d_Qb[mi - 1][r0 + tid] = qred[0][tid] + qred[1][tid] + qred[2][tid] + qred[3][tid];
    }
}

// ================= K3: score + softmax (hot) =================
// grid = 2 sets x 512 rows = 1024 blocks, 256 threads; thread owns m = 2*tid, 2*tid+1
__global__ void __launch_bounds__(256) k3_score(
    const float* __restrict__ s_w1, const float* __restrict__ s_w2)
{
    int set = blockIdx.x >> 9;
    int n = blockIdx.x & 511;
    __shared__ float As[H];
    __shared__ float2 ws[H];   // (wnh, s2h)
    __shared__ float red[16];

    int tid = threadIdx.x;
    if (tid < H) {
        As[tid] = d_A[n * H + tid];
        float wn = s_w1[3 * R * H + tid] * INV_SQRT2;
        float s2 = s_w2[tid] * 0.70710678f;
        ws[tid] = make_float2(wn, s2);
    }
    __syncthreads();

    float nx = d_norm2[0][n];
    float2 ny = *(const float2*)&d_norm2[set + 1][2 * tid];
    float2 g0 = *(const float2*)&d_G[set][0][n * M + 2 * tid];
    float2 g1 = *(const float2*)&d_G[set][1][n * M + 2 * tid];
    float t0 = sqrtf(fmaxf(nx + ny.x - 2.f * (g0.x + g1.x), 0.f));
    float t1 = sqrtf(fmaxf(nx + ny.y - 2.f * (g0.y + g1.y), 0.f));
    float2 qb = *(const float2*)&d_Qb[set][2 * tid];
    float qw = d_Qw;

    float sq0 = 0.f, sn0 = 0.f, sq1 = 0.f, sn1 = 0.f;
    const float2* Bt2 = (const float2*)&d_Bt[set][0];

#pragma unroll 4
    for (int k = 0; k < H; k++) {
        float2 bv = Bt2[k * 256 + tid];
        float a = As[k];
        float2 wsp = ws[k];
        // elem 0
        {
            float p = fmaf(t0, wsp.x, a + bv.x);
            float ap = fabsf(p);
            float dd = fmaf(0.47047f, ap, 1.f);
            float rc; asm("rcp.approx.f32 %0,%1;" : "=f"(rc) : "f"(dd));
            float hh = fmaf(0.7478556f, rc, -0.0958798f);
            hh = fmaf(hh, rc, 0.3480242f);
            float pl = hh * rc;
            float ex = __expf(-p * p);
            float qs = wsp.y * ap;
            sq0 += qs;
            sn0 = fmaf(qs * pl, ex, sn0);
        }
        // elem 1
        {
            float p = fmaf(t1, wsp.x, a + bv.y);
            float ap = fabsf(p);
            float dd = fmaf(0.47047f, ap, 1.f);
            float rc; asm("rcp.approx.f32 %0,%1;" : "=f"(rc) : "f"(dd));
            float hh = fmaf(0.7478556f, rc, -0.0958798f);
            hh = fmaf(hh, rc, 0.3480242f);
            float pl = hh * rc;
            float ex = __expf(-p * p);
            float qs = wsp.y * ap;
            sq1 += qs;
            sn1 = fmaf(qs * pl, ex, sn1);
        }
    }

    // logits (up to a row constant, which softmax ignores)
    float l0 = fmaf(t0, qw, qb.x) + sq0 - sn0;
    float l1 = fmaf(t1, qw, qb.y) + sq1 - sn1;

    // block softmax over 512 values (2 per thread)
    int w = tid >> 5, lane = tid & 31;
    float mx = fmaxf(l0, l1);
#pragma unroll
    for (int o = 16; o; o >>= 1) mx = fmaxf(mx, __shfl_xor_sync(0xFFFFFFFFu, mx, o));
    if (lane == 0) red[w] = mx;
    __syncthreads();
    mx = red[0];
#pragma unroll
    for (int i = 1; i < 8; i++) mx = fmaxf(mx, red[i]);
    float e0 = __expf(l0 - mx), e1 = __expf(l1 - mx);
    float s = e0 + e1;
#pragma unroll
    for (int o = 16; o; o >>= 1) s += __shfl_xor_sync(0xFFFFFFFFu, s, o);
    if (lane == 0) red[8 + w] = s;
    __syncthreads();
    s = red[8];
#pragma unroll
    for (int i = 9; i < 16; i++) s += red[i];
    float inv = 1.f / s;
    *(float2*)&d_W[set][n * M + 2 * tid] = make_float2(e0 * inv, e1 * inv);
}

// ================= K4a: U partials, split-K over M (8 ways), double-buffered =================
// grid = 64 tiles x 8 ms = 512 blocks, 256 threads
__global__ void __launch_bounds__(256) k4a_u()
{
    __shared__ float w_s[2][2][16][36];
    __shared__ float yp_s[2][16][64];
    __shared__ float yn_s[2][16][64];

    int bid = blockIdx.x;
    int ms = bid & 7;
    int tile = bid >> 3;
    int bn = (tile >> 2) * 32;
    int br = (tile & 3) * 64;
    int tid = threadIdx.x;
    int ty = tid >> 4;
    int tx = tid & 15;

    int wset = tid >> 7;
    int wn = (tid & 127) >> 2;
    int wm = (tid & 3) * 4;
    int ykk = tid >> 4;
    int yc = (tid & 15) * 4;

    float acc[2][4];
#pragma unroll
    for (int i = 0; i < 2; i++)
#pragma unroll
        for (int j = 0; j < 4; j++) acc[i][j] = 0.f;

    int mbase = ms * 64;
    float4 wv, ypv, ynv;
    wv  = *(const float4*)&d_W[wset][(bn + wn) * M + mbase + wm];
    ypv = *(const float4*)&d_rep[1][mbase + ykk][br + yc];
    ynv = *(const float4*)&d_rep[2][mbase + ykk][br + yc];
    w_s[0][wset][wm + 0][wn] = wv.x;
    w_s[0][wset][wm + 1][wn] = wv.y;
    w_s[0][wset][wm + 2][wn] = wv.z;
    w_s[0][wset][wm + 3][wn] = wv.w;
    *(float4*)&yp_s[0][ykk][yc] = ypv;
    *(float4*)&yn_s[0][ykk][yc] = ynv;
    __syncthreads();

    int buf = 0;
    for (int mc = 0; mc < 4; mc++) {
        if (mc < 3) {
            int mrow = mbase + (mc + 1) * 16;
            wv  = *(const float4*)&d_W[wset][(bn + wn) * M + mrow + wm];
            ypv = *(const float4*)&d_rep[1][mrow + ykk][br + yc];
            ynv = *(const float4*)&d_rep[2][mrow + ykk][br + yc];
        }
#pragma unroll
        for (int kk = 0; kk < 16; kk++) {
            float wp0 = w_s[buf][0][kk][ty * 2], wp1 = w_s[buf][0][kk][ty * 2 + 1];
            float wq0 = w_s[buf][1][kk][ty * 2], wq1 = w_s[buf][1][kk][ty * 2 + 1];
            float4 yp = *(const float4*)&yp_s[buf][kk][tx * 4];
            float4 yn = *(const float4*)&yn_s[buf][kk][tx * 4];
            float ypa[4] = {yp.x, yp.y, yp.z, yp.w};
            float yna[4] = {yn.x, yn.y, yn.z, yn.w};
#pragma unroll
            for (int j = 0; j < 4; j++) {
                acc[0][j] += wp0 * ypa[j];
                acc[1][j] += wp1 * ypa[j];
                acc[0][j] -= wq0 * yna[j];
                acc[1][j] -= wq1 * yna[j];
            }
        }
        if (mc < 3) {
            __syncthreads();
            int nb = buf ^ 1;
            w_s[nb][wset][wm + 0][wn] = wv.x;
            w_s[nb][wset][wm + 1][wn] = wv.y;
            w_s[nb][wset][wm + 2][wn] = wv.z;
            w_s[nb][wset][wm + 3][wn] = wv.w;
            *(float4*)&yp_s[nb][ykk][yc] = ypv;
            *(float4*)&yn_s[nb][ykk][yc] = ynv;
            __syncthreads();
            buf = nb;
        }
    }
#pragma unroll
    for (int i = 0; i < 2; i++) {
        float4 o = make_float4(acc[i][0], acc[i][1], acc[i][2], acc[i][3]);
        *(float4*)&d_Upart[ms][bn + ty * 2 + i][br + tx * 4] = o;
    }
}

// ================= K4b: out = (sum of 8 U partials) @ out_w =================
__global__ void __launch_bounds__(256) k4b_out(const float* __restrict__ out_w,
                                               float* __restrict__ out)
{
    __shared__ float us[16][36];
    __shared__ float ws[16][64];

    int bid = blockIdx.x;
    int bn = (bid >> 3) * 32;
    int bd = (bid & 7) * 64;
    int tid = threadIdx.x;
    int ty = tid >> 4, tx = tid & 15;

    float acc[2][4];
#pragma unroll
    for (int i = 0; i < 2; i++)
#pragma unroll
        for (int j = 0; j < 4; j++) acc[i][j] = 0.f;

    int un = tid >> 2;
    int uk = (tid & 3) * 4;
    int t2 = tid - 128;
    int wkk = t2 >> 3;
    int wc = (t2 & 7) * 8;

    for (int kc = 0; kc < R / 16; kc++) {
        float4 uv; float4 wv0, wv1;
        if (tid < 128) {
            float4 p[8];
#pragma unroll
            for (int q = 0; q < 8; q++)
                p[q] = *(const float4*)&d_Upart[q][bn + un][kc * 16 + uk];
            uv = p[0];
#pragma unroll
            for (int q = 1; q < 8; q++) {
                uv.x += p[q].x; uv.y += p[q].y; uv.z += p[q].z; uv.w += p[q].w;
            }
        } else {
            wv0 = *(const float4*)&out_w[(kc * 16 + wkk) * D + bd + wc];
            wv1 = *(const float4*)&out_w[(kc * 16 + wkk) * D + bd + wc + 4];
        }
        __syncthreads();
        if (tid < 128) {
            us[uk + 0][un] = uv.x;
            us[uk + 1][un] = uv.y;
            us[uk + 2][un] = uv.z;
            us[uk + 3][un] = uv.w;
        } else {
            *(float4*)&ws[wkk][wc] = wv0;
            *(float4*)&ws[wkk][wc + 4] = wv1;
        }
        __syncthreads();
#pragma unroll
        for (int kk = 0; kk < 16; kk++) {
            float u0 = us[kk][ty * 2], u1 = us[kk][ty * 2 + 1];
            float4 w4 = *(const float4*)&ws[kk][tx * 4];
            float wa[4] = {w4.x, w4.y, w4.z, w4.w};
#pragma unroll
            for (int j = 0; j < 4; j++) {
                acc[0][j] += u0 * wa[j];
                acc[1][j] += u1 * wa[j];
            }
        }
    }
#pragma unroll
    for (int i = 0; i < 2; i++) {
        float4 o = make_float4(acc[i][0], acc[i][1], acc[i][2], acc[i][3]);
        *(float4*)&out[(bn + ty * 2 + i) * D + bd + tx * 4] = o;
    }
}

// ---------------- launch ----------------
extern "C" void kernel_launch(void* const* d_in, const int* in_sizes, int n_in,
                              void* d_out, int out_size)
{
    const float* feat_x  = (const float*)d_in[0];
    const float* feat_pos= (const float*)d_in[1];
    const float* feat_neg= (const float*)d_in[2];
    const float* g_w1    = (const float*)d_in[3];
    const float* g_b1    = (const float*)d_in[4];
    const float* g_w2    = (const float*)d_in[5];
    const float* g_b2    = (const float*)d_in[6];
    const float* out_w   = (const float*)d_in[7];
    const float* s_w1    = (const float*)d_in[8];
    const float* s_b1    = (const float*)d_in[9];
    const float* s_w2    = (const float*)d_in[10];
    float* out = (float*)d_out;
    (void)in_sizes; (void)n_in; (void)out_size;

    k1_gmlp<<<225, 256>>>(feat_x, feat_pos, feat_neg, g_w1, g_b1, g_w2, g_b2, s_w1, s_w2);
    k2_gram_ab<<<448, 256>>>(s_b1, s_w2);
    k3_score<<<1024, 256>>>(s_w1, s_w2);
    k4a_u<<<512, 256>>>();
    k4b_out<<<128, 256>>>(out_w, out);
}